// round 2
// baseline (speedup 1.0000x reference)
#include <cuda_runtime.h>

#define B_ 8
#define C_ 384
#define L_ 1024
#define H_ 6
#define D_ 64
#define NW_ 9   // 2*window+1

// Scratch (allocation-free rule: device globals)
__device__ float g_q[B_*C_*L_];
__device__ float g_k[B_*C_*L_];
__device__ float g_v[B_*C_*L_];
__device__ float g_res[B_*C_*L_];

// ---------------------------------------------------------------------------
// Projection GEMM: Y[b][o][l] = sum_c W[o][c] * X[b][c][l] + bias[o]
// M=C_=384 (o), N=L_=1024 (l), K=C_=384 (c). 64x64 tiles, 16-deep k-tiles.
// ---------------------------------------------------------------------------
__global__ __launch_bounds__(256) void proj_kernel(const float* __restrict__ W,
                                                   const float* __restrict__ bias,
                                                   const float* __restrict__ X,
                                                   float* __restrict__ Y) {
    __shared__ float Ws[64][16];
    __shared__ float Xs[16][64];
    const int b  = blockIdx.z;
    const int o0 = blockIdx.y * 64;
    const int l0 = blockIdx.x * 64;
    const int tid = threadIdx.x;           // 0..255
    const int tx = tid & 15, ty = tid >> 4;
    const float* Xb = X + (size_t)b * C_ * L_;

    float acc[4][4];
#pragma unroll
    for (int r = 0; r < 4; r++)
#pragma unroll
        for (int c = 0; c < 4; c++) acc[r][c] = 0.f;

    for (int c0 = 0; c0 < C_; c0 += 16) {
#pragma unroll
        for (int p = 0; p < 4; p++) {
            int e = tid + p * 256;
            int i = e >> 4, kk = e & 15;
            Ws[i][kk] = W[(size_t)(o0 + i) * C_ + c0 + kk];
        }
#pragma unroll
        for (int p = 0; p < 4; p++) {
            int e = tid + p * 256;
            int kk = e >> 6, j = e & 63;
            Xs[kk][j] = Xb[(size_t)(c0 + kk) * L_ + l0 + j];
        }
        __syncthreads();
#pragma unroll
        for (int kk = 0; kk < 16; kk++) {
            float a[4], bb[4];
#pragma unroll
            for (int r = 0; r < 4; r++) a[r] = Ws[ty * 4 + r][kk];
#pragma unroll
            for (int c = 0; c < 4; c++) bb[c] = Xs[kk][tx * 4 + c];
#pragma unroll
            for (int r = 0; r < 4; r++)
#pragma unroll
                for (int c = 0; c < 4; c++) acc[r][c] += a[r] * bb[c];
        }
        __syncthreads();
    }

#pragma unroll
    for (int r = 0; r < 4; r++) {
        int o = o0 + ty * 4 + r;
        float bv = bias[o];
#pragma unroll
        for (int c = 0; c < 4; c++)
            Y[(size_t)b * C_ * L_ + (size_t)o * L_ + l0 + tx * 4 + c] = acc[r][c] + bv;
    }
}

// ---------------------------------------------------------------------------
// Flash attention with 9-wide relative band.
//   score[i][j] = (q_i.k_j + [|j-i|<=4] q_i.Ek[j-i+4]) * scale
//   res[i]      = sum_j p_ij * v_j + sum_{|d|<=4} p[i,i+d] * Ev[d+4]
// Block: 64 query rows for one (b,h). 256 threads (16x16). K-tiles of 32.
// ---------------------------------------------------------------------------
__global__ __launch_bounds__(256) void attn_kernel(const float* __restrict__ erk,
                                                   const float* __restrict__ erv) {
    __shared__ float Qt[64][65];   // [dim][qpos]
    __shared__ float Kt[64][33];   // [dim][kpos]
    __shared__ float Vt[64][33];   // [dim][kpos]
    __shared__ float Ps[64][33];   // [qpos][kpos]
    __shared__ float Eks[NW_][64]; // [delta][dim]
    __shared__ float Evs[NW_][64];
    __shared__ float qEk[64][NW_]; // [qrow][delta]

    const int tid = threadIdx.x;
    const int tx = tid & 15, ty = tid >> 4;
    const int i0 = blockIdx.x * 64;
    const int bh = blockIdx.y;
    const int b = bh / H_, h = bh % H_;

    const float* Qg = g_q + (size_t)(b * C_ + h * D_) * L_;
    const float* Kg = g_k + (size_t)(b * C_ + h * D_) * L_;
    const float* Vg = g_v + (size_t)(b * C_ + h * D_) * L_;

    // Load Q tile (coalesced over qpos), and the two 9x64 embedding tables.
    for (int e = tid; e < 64 * 64; e += 256) {
        int r = e >> 6, i = e & 63;
        Qt[r][i] = Qg[(size_t)r * L_ + i0 + i];
    }
    for (int e = tid; e < NW_ * 64; e += 256) {
        int dd = e >> 6, r = e & 63;
        Eks[dd][r] = erk[(h * NW_ + dd) * 64 + r];
        Evs[dd][r] = erv[(h * NW_ + dd) * 64 + r];
    }
    __syncthreads();

    // Precompute qEk[i][dd] = q_i . Ek[dd]  (64x9 dots of length 64)
    for (int idx = tid; idx < 64 * NW_; idx += 256) {
        int dd = idx >> 6, i = idx & 63;
        float s = 0.f;
#pragma unroll
        for (int r = 0; r < 64; r++) s += Qt[r][i] * Eks[dd][r];
        qEk[i][dd] = s;
    }
    // (visibility of qEk handled by the sync at the top of the first k-tile)

    float m_i[4], l_i[4], Oacc[4][4];
#pragma unroll
    for (int ii = 0; ii < 4; ii++) {
        m_i[ii] = -1e30f; l_i[ii] = 0.f;
#pragma unroll
        for (int rr = 0; rr < 4; rr++) Oacc[ii][rr] = 0.f;
    }

    const float scale = 0.125f;  // 1/sqrt(64)

    for (int j0 = 0; j0 < L_; j0 += 32) {
        __syncthreads();  // prev PV done; also fences qEk on first iter
        // Load K,V tiles (coalesced over kpos)
        for (int e = tid; e < 64 * 32; e += 256) {
            int r = e >> 5, j = e & 31;
            Kt[r][j] = Kg[(size_t)r * L_ + j0 + j];
            Vt[r][j] = Vg[(size_t)r * L_ + j0 + j];
        }
        __syncthreads();

        // S = Q.K^T : rows ty*4+ii, cols tx*2+jj
        float S[4][2];
#pragma unroll
        for (int ii = 0; ii < 4; ii++) { S[ii][0] = 0.f; S[ii][1] = 0.f; }
#pragma unroll 16
        for (int r = 0; r < 64; r++) {
            float a[4], bv0, bv1;
#pragma unroll
            for (int ii = 0; ii < 4; ii++) a[ii] = Qt[r][ty * 4 + ii];
            bv0 = Kt[r][tx * 2];
            bv1 = Kt[r][tx * 2 + 1];
#pragma unroll
            for (int ii = 0; ii < 4; ii++) {
                S[ii][0] += a[ii] * bv0;
                S[ii][1] += a[ii] * bv1;
            }
        }
        // Relative-K band bias + scale
#pragma unroll
        for (int ii = 0; ii < 4; ii++) {
            int qi = i0 + ty * 4 + ii;
#pragma unroll
            for (int jj = 0; jj < 2; jj++) {
                int kj = j0 + tx * 2 + jj;
                int d = kj - qi;
                float bias = (d >= -4 && d <= 4) ? qEk[ty * 4 + ii][d + 4] : 0.f;
                S[ii][jj] = (S[ii][jj] + bias) * scale;
            }
        }

        // Online softmax. Each row's 64 columns live in the 16 lanes of a
        // half-warp (tid = ty*16+tx; lanes [0..15]/[16..31] have fixed ty),
        // so xor-shuffles 8,4,2,1 reduce within the row group.
        float alpha[4];
#pragma unroll
        for (int ii = 0; ii < 4; ii++) {
            float tm = fmaxf(S[ii][0], S[ii][1]);
#pragma unroll
            for (int o = 8; o >= 1; o >>= 1)
                tm = fmaxf(tm, __shfl_xor_sync(0xffffffffu, tm, o));
            float mnew = fmaxf(m_i[ii], tm);
            float p0 = __expf(S[ii][0] - mnew);
            float p1 = __expf(S[ii][1] - mnew);
            S[ii][0] = p0; S[ii][1] = p1;
            float ts = p0 + p1;
#pragma unroll
            for (int o = 8; o >= 1; o >>= 1)
                ts += __shfl_xor_sync(0xffffffffu, ts, o);
            float a2 = __expf(m_i[ii] - mnew);
            alpha[ii] = a2;
            l_i[ii] = l_i[ii] * a2 + ts;
            m_i[ii] = mnew;
        }
#pragma unroll
        for (int ii = 0; ii < 4; ii++)
#pragma unroll
            for (int rr = 0; rr < 4; rr++) Oacc[ii][rr] *= alpha[ii];

        // Stage P for the PV GEMM
#pragma unroll
        for (int ii = 0; ii < 4; ii++) {
            Ps[ty * 4 + ii][tx * 2]     = S[ii][0];
            Ps[ty * 4 + ii][tx * 2 + 1] = S[ii][1];
        }
        __syncthreads();

        // O += P.V : rows ty*4+ii, dims tx*4+rr
#pragma unroll 8
        for (int j = 0; j < 32; j++) {
            float p[4], vv[4];
#pragma unroll
            for (int ii = 0; ii < 4; ii++) p[ii] = Ps[ty * 4 + ii][j];
#pragma unroll
            for (int rr = 0; rr < 4; rr++) vv[rr] = Vt[tx * 4 + rr][j];
#pragma unroll
            for (int ii = 0; ii < 4; ii++)
#pragma unroll
                for (int rr = 0; rr < 4; rr++) Oacc[ii][rr] += p[ii] * vv[rr];
        }

        // Relative-V band: O[i] += p[i, i+d] * Ev[d+4] for in-tile columns.
        if (j0 + 31 >= i0 - 4 && j0 <= i0 + 63 + 4) {
#pragma unroll
            for (int ii = 0; ii < 4; ii++) {
                int qi = i0 + ty * 4 + ii;
#pragma unroll
                for (int dd = 0; dd < NW_; dd++) {
                    int j = qi + dd - 4 - j0;
                    if (j >= 0 && j < 32) {
                        float pv = Ps[ty * 4 + ii][j];
#pragma unroll
                        for (int rr = 0; rr < 4; rr++)
                            Oacc[ii][rr] += pv * Evs[dd][tx * 4 + rr];
                    }
                }
            }
        }
    }
    __syncthreads();

    // Epilogue: normalize, stage transposed in Qt, coalesced store.
    float* Rg = g_res + (size_t)(b * C_ + h * D_) * L_;
#pragma unroll
    for (int ii = 0; ii < 4; ii++) {
        float inv = 1.0f / l_i[ii];
#pragma unroll
        for (int rr = 0; rr < 4; rr++)
            Qt[tx * 4 + rr][ty * 4 + ii] = Oacc[ii][rr] * inv;
    }
    __syncthreads();
    for (int e = tid; e < 64 * 64; e += 256) {
        int r = e >> 6, i = e & 63;
        Rg[(size_t)r * L_ + i0 + i] = Qt[r][i];
    }
}

// ---------------------------------------------------------------------------
extern "C" void kernel_launch(void* const* d_in, const int* in_sizes, int n_in,
                              void* d_out, int out_size) {
    const float* x   = (const float*)d_in[0];
    const float* wq  = (const float*)d_in[1];
    const float* bq  = (const float*)d_in[2];
    const float* wk  = (const float*)d_in[3];
    const float* bk  = (const float*)d_in[4];
    const float* wv  = (const float*)d_in[5];
    const float* bv  = (const float*)d_in[6];
    const float* wo  = (const float*)d_in[7];
    const float* bo  = (const float*)d_in[8];
    const float* erk = (const float*)d_in[9];
    const float* erv = (const float*)d_in[10];
    float* out = (float*)d_out;

    float *gq, *gk, *gv, *gres;
    cudaGetSymbolAddress((void**)&gq,   g_q);
    cudaGetSymbolAddress((void**)&gk,   g_k);
    cudaGetSymbolAddress((void**)&gv,   g_v);
    cudaGetSymbolAddress((void**)&gres, g_res);

    dim3 pgrid(L_ / 64, C_ / 64, B_);  // (16, 6, 8)
    proj_kernel<<<pgrid, 256>>>(wq, bq, x, gq);
    proj_kernel<<<pgrid, 256>>>(wk, bk, x, gk);
    proj_kernel<<<pgrid, 256>>>(wv, bv, x, gv);

    dim3 agrid(L_ / 64, B_ * H_);      // (16, 48)
    attn_kernel<<<agrid, 256>>>(erk, erv);

    proj_kernel<<<pgrid, 256>>>(wo, bo, gres, out);
}

// round 3
// speedup vs baseline: 1.1539x; 1.1539x over previous
#include <cuda_runtime.h>

#define B_ 8
#define C_ 384
#define L_ 1024
#define H_ 6
#define D_ 64
#define NW_ 9   // 2*window+1

// Scratch (allocation-free rule: device globals)
__device__ float g_q[B_*C_*L_];
__device__ float g_k[B_*C_*L_];
__device__ float g_v[B_*C_*L_];
__device__ float g_res[B_*C_*L_];

// ---------------------------------------------------------------------------
// Projection GEMM: Y[b][o][l] = sum_c W[o][c] * X[b][c][l] + bias[o]
// 64x64 tiles, ktile=16, 4x4 microtile, float4 everywhere.
// ---------------------------------------------------------------------------
__global__ __launch_bounds__(256) void proj_kernel(const float* __restrict__ W,
                                                   const float* __restrict__ bias,
                                                   const float* __restrict__ X,
                                                   float* __restrict__ Y) {
    __shared__ float WsT[16][68];   // [c][o]  (transposed at load)
    __shared__ float Xs[16][68];    // [c][l]
    const int b  = blockIdx.z;
    const int o0 = blockIdx.y * 64;
    const int l0 = blockIdx.x * 64;
    const int tid = threadIdx.x;           // 0..255
    const int tx = tid & 15, ty = tid >> 4;
    const float* Xb = X + (size_t)b * C_ * L_;

    float acc[4][4];
#pragma unroll
    for (int r = 0; r < 4; r++)
#pragma unroll
        for (int c = 0; c < 4; c++) acc[r][c] = 0.f;

    // W load mapping: i = o index, kkb = c sub-block
    const int wi  = tid >> 2;          // 0..63
    const int kkb = (tid & 3) * 4;     // 0,4,8,12
    // X load mapping
    const int xk = tid >> 4;           // 0..15
    const int xj = (tid & 15) * 4;     // 0..60

    for (int c0 = 0; c0 < C_; c0 += 16) {
        float4 w4 = *(const float4*)(W + (size_t)(o0 + wi) * C_ + c0 + kkb);
        float4 x4 = *(const float4*)(Xb + (size_t)(c0 + xk) * L_ + l0 + xj);
        WsT[kkb + 0][wi] = w4.x;
        WsT[kkb + 1][wi] = w4.y;
        WsT[kkb + 2][wi] = w4.z;
        WsT[kkb + 3][wi] = w4.w;
        *(float4*)&Xs[xk][xj] = x4;
        __syncthreads();
#pragma unroll
        for (int kk = 0; kk < 16; kk++) {
            float4 a4 = *(const float4*)&WsT[kk][ty * 4];
            float4 b4 = *(const float4*)&Xs[kk][tx * 4];
            float a[4] = {a4.x, a4.y, a4.z, a4.w};
            float bb[4] = {b4.x, b4.y, b4.z, b4.w};
#pragma unroll
            for (int r = 0; r < 4; r++)
#pragma unroll
                for (int c = 0; c < 4; c++) acc[r][c] += a[r] * bb[c];
        }
        __syncthreads();
    }

#pragma unroll
    for (int r = 0; r < 4; r++) {
        int o = o0 + ty * 4 + r;
        float bv = bias[o];
        float4 out4 = make_float4(acc[r][0] + bv, acc[r][1] + bv,
                                  acc[r][2] + bv, acc[r][3] + bv);
        *(float4*)(Y + (size_t)b * C_ * L_ + (size_t)o * L_ + l0 + tx * 4) = out4;
    }
}

// ---------------------------------------------------------------------------
// Flash attention with 9-wide relative band.
//   score[i][j] = (q_i.k_j + [|j-i|<=4] q_i.Ek[j-i+4]) * scale
//   res[i]      = sum_j p_ij * v_j + sum_{|d|<=4} p[i,i+d] * Ev[d+4]
// Block: 64 query rows for one (b,h). 256 threads (16x16), 4x4 microtiles,
// K-tiles of 64. Dynamic smem (~74KB).
// ---------------------------------------------------------------------------
__global__ __launch_bounds__(256, 2) void attn_kernel(const float* __restrict__ erk,
                                                      const float* __restrict__ erv) {
    extern __shared__ float sm[];
    float (*Qt)[68]  = (float(*)[68])(sm);            // [dim][qpos]   64x68
    float (*Kt)[68]  = (float(*)[68])(sm + 4352);     // [dim][kpos]   64x68
    float (*Vt)[65]  = (float(*)[65])(sm + 8704);     // [dim][kpos]   64x65 (odd pad)
    float (*Ps)[68]  = (float(*)[68])(sm + 12864);    // [qpos][kpos]  64x68
    float (*Eks)[64] = (float(*)[64])(sm + 17216);    // [delta][dim]
    float (*Evs)[64] = (float(*)[64])(sm + 17792);
    float (*qEk)[NW_] = (float(*)[NW_])(sm + 18368);  // [qrow][delta]

    const int tid = threadIdx.x;
    const int tx = tid & 15, ty = tid >> 4;
    const int i0 = blockIdx.x * 64;
    const int bh = blockIdx.y;
    const int b = bh / H_, h = bh % H_;

    const float* Qg = g_q + (size_t)(b * C_ + h * D_) * L_;
    const float* Kg = g_k + (size_t)(b * C_ + h * D_) * L_;
    const float* Vg = g_v + (size_t)(b * C_ + h * D_) * L_;

    // Load Q tile (float4 coalesced) + embedding tables
#pragma unroll
    for (int it = 0; it < 4; it++) {
        int g = tid + it * 256;
        int r = g >> 4, i4 = (g & 15) * 4;
        float4 q4 = *(const float4*)(Qg + (size_t)r * L_ + i0 + i4);
        *(float4*)&Qt[r][i4] = q4;
    }
    for (int e = tid; e < NW_ * 64; e += 256) {
        int dd = e >> 6, r = e & 63;
        Eks[dd][r] = erk[(h * NW_ + dd) * 64 + r];
        Evs[dd][r] = erv[(h * NW_ + dd) * 64 + r];
    }
    __syncthreads();

    // qEk[i][dd] = q_i . Ek[dd]
    for (int idx = tid; idx < 64 * NW_; idx += 256) {
        int dd = idx >> 6, i = idx & 63;
        float s = 0.f;
#pragma unroll
        for (int r = 0; r < 64; r++) s += Qt[r][i] * Eks[dd][r];
        qEk[i][dd] = s;
    }
    // visibility: first sync inside the tile loop fences qEk

    float m_i[4], l_i[4], Oacc[4][4];
#pragma unroll
    for (int ii = 0; ii < 4; ii++) {
        m_i[ii] = -1e30f; l_i[ii] = 0.f;
#pragma unroll
        for (int rr = 0; rr < 4; rr++) Oacc[ii][rr] = 0.f;
    }

    const float scale = 0.125f;  // 1/sqrt(64)

    for (int j0 = 0; j0 < L_; j0 += 64) {
        __syncthreads();  // prev tile's PV reads of Kt/Vt done; fences qEk (iter 0)
        // Load K,V tiles (float4 coalesced); V stored with odd pad (scalar stores)
#pragma unroll
        for (int it = 0; it < 4; it++) {
            int g = tid + it * 256;
            int r = g >> 4, j4 = (g & 15) * 4;
            float4 k4 = *(const float4*)(Kg + (size_t)r * L_ + j0 + j4);
            *(float4*)&Kt[r][j4] = k4;
            float4 v4 = *(const float4*)(Vg + (size_t)r * L_ + j0 + j4);
            Vt[r][j4 + 0] = v4.x;
            Vt[r][j4 + 1] = v4.y;
            Vt[r][j4 + 2] = v4.z;
            Vt[r][j4 + 3] = v4.w;
        }
        __syncthreads();

        // S = Q.K^T : rows ty*4+ii, cols tx*4+jj
        float S[4][4];
#pragma unroll
        for (int ii = 0; ii < 4; ii++)
#pragma unroll
            for (int jj = 0; jj < 4; jj++) S[ii][jj] = 0.f;
#pragma unroll 16
        for (int r = 0; r < 64; r++) {
            float4 q4 = *(const float4*)&Qt[r][ty * 4];
            float4 k4 = *(const float4*)&Kt[r][tx * 4];
            float a[4] = {q4.x, q4.y, q4.z, q4.w};
            float bb[4] = {k4.x, k4.y, k4.z, k4.w};
#pragma unroll
            for (int ii = 0; ii < 4; ii++)
#pragma unroll
                for (int jj = 0; jj < 4; jj++) S[ii][jj] += a[ii] * bb[jj];
        }

        // Relative-K band bias + scale
#pragma unroll
        for (int ii = 0; ii < 4; ii++) {
            int qi = i0 + ty * 4 + ii;
#pragma unroll
            for (int jj = 0; jj < 4; jj++) {
                int kj = j0 + tx * 4 + jj;
                int d = kj - qi;
                float bias = (d >= -4 && d <= 4) ? qEk[ty * 4 + ii][d + 4] : 0.f;
                S[ii][jj] = (S[ii][jj] + bias) * scale;
            }
        }

        // Online softmax: each row's 64 cols live in 16 lanes (fixed ty within
        // half-warp), xor-shuffles 8,4,2,1 reduce across tx.
        float alpha[4];
#pragma unroll
        for (int ii = 0; ii < 4; ii++) {
            float tm = fmaxf(fmaxf(S[ii][0], S[ii][1]), fmaxf(S[ii][2], S[ii][3]));
#pragma unroll
            for (int o = 8; o >= 1; o >>= 1)
                tm = fmaxf(tm, __shfl_xor_sync(0xffffffffu, tm, o));
            float mnew = fmaxf(m_i[ii], tm);
            float ts = 0.f;
#pragma unroll
            for (int jj = 0; jj < 4; jj++) {
                S[ii][jj] = __expf(S[ii][jj] - mnew);
                ts += S[ii][jj];
            }
#pragma unroll
            for (int o = 8; o >= 1; o >>= 1)
                ts += __shfl_xor_sync(0xffffffffu, ts, o);
            float a2 = __expf(m_i[ii] - mnew);
            alpha[ii] = a2;
            l_i[ii] = l_i[ii] * a2 + ts;
            m_i[ii] = mnew;
        }
#pragma unroll
        for (int ii = 0; ii < 4; ii++)
#pragma unroll
            for (int rr = 0; rr < 4; rr++) Oacc[ii][rr] *= alpha[ii];

        // Stage P (row qi is produced and consumed by the same half-warp)
#pragma unroll
        for (int ii = 0; ii < 4; ii++)
            *(float4*)&Ps[ty * 4 + ii][tx * 4] =
                make_float4(S[ii][0], S[ii][1], S[ii][2], S[ii][3]);
        __syncwarp();

        // O += P.V : rows ty*4+ii, dims tx*4+rr
#pragma unroll 8
        for (int j = 0; j < 64; j++) {
            float p[4], vv[4];
#pragma unroll
            for (int ii = 0; ii < 4; ii++) p[ii] = Ps[ty * 4 + ii][j];   // broadcast
#pragma unroll
            for (int rr = 0; rr < 4; rr++) vv[rr] = Vt[tx * 4 + rr][j];  // conflict-free (pad 65)
#pragma unroll
            for (int ii = 0; ii < 4; ii++)
#pragma unroll
                for (int rr = 0; rr < 4; rr++) Oacc[ii][rr] += p[ii] * vv[rr];
        }

        // Relative-V band: O[i] += p[i, i+d] * Ev[d+4] for in-tile columns.
        if (j0 + 63 >= i0 - 4 && j0 <= i0 + 67) {
#pragma unroll
            for (int ii = 0; ii < 4; ii++) {
                int qi = i0 + ty * 4 + ii;
#pragma unroll
                for (int dd = 0; dd < NW_; dd++) {
                    int j = qi + dd - 4 - j0;
                    if (j >= 0 && j < 64) {
                        float pv = Ps[ty * 4 + ii][j];
#pragma unroll
                        for (int rr = 0; rr < 4; rr++)
                            Oacc[ii][rr] += pv * Evs[dd][tx * 4 + rr];
                    }
                }
            }
        }
    }
    __syncthreads();

    // Epilogue: normalize, stage transposed in Qt, coalesced store.
    float* Rg = g_res + (size_t)(b * C_ + h * D_) * L_;
#pragma unroll
    for (int ii = 0; ii < 4; ii++) {
        float inv = 1.0f / l_i[ii];
#pragma unroll
        for (int rr = 0; rr < 4; rr++)
            Qt[tx * 4 + rr][ty * 4 + ii] = Oacc[ii][rr] * inv;
    }
    __syncthreads();
#pragma unroll
    for (int it = 0; it < 4; it++) {
        int g = tid + it * 256;
        int r = g >> 4, i4 = (g & 15) * 4;
        float4 o4 = *(const float4*)&Qt[r][i4];
        *(float4*)(Rg + (size_t)r * L_ + i0 + i4) = o4;
    }
}

// ---------------------------------------------------------------------------
extern "C" void kernel_launch(void* const* d_in, const int* in_sizes, int n_in,
                              void* d_out, int out_size) {
    const float* x   = (const float*)d_in[0];
    const float* wq  = (const float*)d_in[1];
    const float* bq  = (const float*)d_in[2];
    const float* wk  = (const float*)d_in[3];
    const float* bk  = (const float*)d_in[4];
    const float* wv  = (const float*)d_in[5];
    const float* bv  = (const float*)d_in[6];
    const float* wo  = (const float*)d_in[7];
    const float* bo  = (const float*)d_in[8];
    const float* erk = (const float*)d_in[9];
    const float* erv = (const float*)d_in[10];
    float* out = (float*)d_out;

    float *gq, *gk, *gv, *gres;
    cudaGetSymbolAddress((void**)&gq,   g_q);
    cudaGetSymbolAddress((void**)&gk,   g_k);
    cudaGetSymbolAddress((void**)&gv,   g_v);
    cudaGetSymbolAddress((void**)&gres, g_res);

    const int attn_smem = 18944 * 4;  // 75776 bytes
    cudaFuncSetAttribute(attn_kernel, cudaFuncAttributeMaxDynamicSharedMemorySize,
                         attn_smem);

    dim3 pgrid(L_ / 64, C_ / 64, B_);  // (16, 6, 8)
    proj_kernel<<<pgrid, 256>>>(wq, bq, x, gq);
    proj_kernel<<<pgrid, 256>>>(wk, bk, x, gk);
    proj_kernel<<<pgrid, 256>>>(wv, bv, x, gv);

    dim3 agrid(L_ / 64, B_ * H_);      // (16, 48)
    attn_kernel<<<agrid, 256, attn_smem>>>(erk, erv);

    proj_kernel<<<pgrid, 256>>>(wo, bo, gres, out);
}